// round 16
// baseline (speedup 1.0000x reference)
#include <cuda_runtime.h>

// ForwardKinematics: B=65536, N=24.
// R15: no input staging. Chain lanes read R and j straight from gmem with
// quad-broadcast scalar LDG; per-SM live input (~74KB) fits L1D, so reads
// after first touch are L1 hits and DRAM sees exactly the input bytes.
// This unlocks BPW=8 (every phase-B instruction serves 8 batches) together
// with 8 CTAs/SM (smem is only sT, 9.5KB). Chain math = proven R14
// 4-slot-ring + jring recurrence. rel rows stored direct via STG.128;
// posed joints staged in sT and written coalesced in phase C.

#define THREADS 128
#define MB 32            // batches per block (8 per warp)
#define BPW 8            // batches per warp

static constexpr int NJ   = 24;
static constexpr int TSTR = 76;    // t floats per batch in sT (72 + 4 pad), 19 x 16B
static constexpr int SMEM_BYTES = MB * TSTR * 4;   // 9728 B

__global__ __launch_bounds__(THREADS, 8)
void fk_kernel(const float* __restrict__ rot,
               const float* __restrict__ jnt,
               float* __restrict__ out_pj,
               float* __restrict__ out_rel)
{
    extern __shared__ float sm[];
    float* sT = sm;                    // [MB][TSTR] global t (for posed_joints)

    const int tid  = threadIdx.x;
    const int warp = tid >> 5;
    const int lane = tid & 31;
    const int wb   = warp * BPW;
    const int gB0  = blockIdx.x * MB + wb;       // warp's first batch (global)

    // ------- Phase B: chain walk straight from gmem (8 batches x 4 rows) -------
    {
        constexpr int PAR[NJ]  = {-1,0,0,0,1,2,3,4,5,6,7,8,9,9,9,12,13,14,16,17,18,19,20,21};
        // static 4-slot ring from liveness of PARENTS (max 4 live; -1 = leaf)
        constexpr int SLOT[NJ] = { 0,1,2,3,0,1,2,3,0,1,-1,-1,2,3,0,-1,2,3,0,1,2,3,-1,-1};
        const int  bl     = lane >> 2;          // 0..7 local batch
        const int  r      = lane & 3;
        const bool active = (r < 3);
        float ring[4][4];                       // [slot][Rg_r0,Rg_r1,Rg_r2,t_r]
        float jring[4][3];                      // [slot][j0,j1,j2]
        const float* mR = rot + (size_t)(gB0 + bl) * 216;   // quad-broadcast LDG
        const float* mJ = jnt + (size_t)(gB0 + bl) * 72;
        float*       mT = sT + (wb + bl) * TSTR;
        float4* relW = reinterpret_cast<float4*>(out_rel) + (size_t)(gB0 + bl) * 96;

        #pragma unroll
        for (int i = 0; i < NJ; ++i) {
            float4 v;
            if (active) {
                float row[4];
                const float j0 = mJ[i * 3 + 0];
                const float j1 = mJ[i * 3 + 1];
                const float j2 = mJ[i * 3 + 2];
                if (i == 0) {
                    row[0] = mR[r * 3 + 0];
                    row[1] = mR[r * 3 + 1];
                    row[2] = mR[r * 3 + 2];
                    row[3] = (r == 0) ? j0 : (r == 1) ? j1 : j2;
                } else {
                    const int ps = SLOT[PAR[i]];            // constexpr after unroll
                    const float a0 = ring[ps][0], a1 = ring[ps][1], a2 = ring[ps][2];
                    const float l00 = mR[i*9+0], l01 = mR[i*9+1], l02 = mR[i*9+2];
                    const float l10 = mR[i*9+3], l11 = mR[i*9+4], l12 = mR[i*9+5];
                    const float l20 = mR[i*9+6], l21 = mR[i*9+7], l22 = mR[i*9+8];
                    const float rel0 = j0 - jring[ps][0];
                    const float rel1 = j1 - jring[ps][1];
                    const float rel2 = j2 - jring[ps][2];
                    row[0] = a0 * l00 + a1 * l10 + a2 * l20;
                    row[1] = a0 * l01 + a1 * l11 + a2 * l21;
                    row[2] = a0 * l02 + a1 * l12 + a2 * l22;
                    row[3] = ring[ps][3] + a0 * rel0 + a1 * rel1 + a2 * rel2;
                }
                if (SLOT[i] >= 0) {                         // leaves skip ring writes
                    const int s = SLOT[i];
                    #pragma unroll
                    for (int k = 0; k < 4; ++k) ring[s][k] = row[k];
                    jring[s][0] = j0; jring[s][1] = j1; jring[s][2] = j2;
                }
                mT[i * 3 + r] = row[3];                     // for posed_joints
                v = make_float4(row[0], row[1], row[2],
                                row[3] - (row[0]*j0 + row[1]*j1 + row[2]*j2));
            } else {
                v = make_float4(0.f, 0.f, 0.f, 1.f);        // bottom row
            }
            relW[i * 4 + r] = v;                            // direct rel store
        }
    }
    __syncwarp();   // sT written by chain lanes, read below with different mapping

    // ---------------- Phase C: coalesced posed-joints copy (LDS.128) ----------------
    {
        const float4* sT4 = reinterpret_cast<const float4*>(sT);   // batch stride 19 f4
        float4* pj4 = reinterpret_cast<float4*>(out_pj) + (size_t)gB0 * 18;
        #pragma unroll
        for (int it = 0; it < 5; ++it) {                   // 8*18 = 144 float4
            int idx = lane + it * 32;
            if (idx < BPW * 18) {
                int b = wb + idx / 18, rf = idx % 18;
                pj4[idx] = sT4[b * 19 + rf];
            }
        }
    }
}

extern "C" void kernel_launch(void* const* d_in, const int* in_sizes, int n_in,
                              void* d_out, int out_size)
{
    const float* rot = (const float*)d_in[0];
    const float* jnt = (const float*)d_in[1];
    float* out = (float*)d_out;

    const long long B = 65536;
    float* out_pj  = out;
    float* out_rel = out + (size_t)B * NJ * 3;

    cudaFuncSetAttribute(fk_kernel, cudaFuncAttributeMaxDynamicSharedMemorySize, SMEM_BYTES);

    const int grid = (int)(B / MB);   // 2048 blocks
    fk_kernel<<<grid, THREADS, SMEM_BYTES>>>(rot, jnt, out_pj, out_rel);
}

// round 17
// speedup vs baseline: 1.6331x; 1.6331x over previous
#include <cuda_runtime.h>

// ForwardKinematics: B=65536, N=24.
// R16: role-split CTA. MB=16, smem 23.8KB -> 8 CTAs/SM (32 warps).
//   A: ALL 4 warps stage rot+jnt coalesced (float4, padded strides).
//   B: warps 0-1 only, BPW=8: 16 batches x 4 rows = 64 lanes; every broadcast
//      LDS / FMA serves 8 batches (half the per-batch cost of R10/R14).
//      Chain math = proven R14 static 4-slot ring + jring; rel rows stored
//      direct via STG.128; t staged to sT.
//   C: ALL warps write posed joints coalesced from sT.
// Bank math: R stride 220 f -> 28*bl%32 distinct for bl=0..7 (and 8..15);
//            J/T stride 76 f -> 12*bl%32 distinct.

#define THREADS 128
#define MB 16            // batches per block
#define NCHAIN 64        // chain threads (warps 0-1): 16 batches x 4 rows

static constexpr int NJ   = 24;
static constexpr int RSTR = 220;   // 216 + 4 pad floats = 55 x 16B
static constexpr int JSTR = 76;    // 72 + 4 pad = 19 x 16B
static constexpr int TSTR = 76;    // global t rows
static constexpr int SMEM_FLOATS = MB * (RSTR + JSTR + TSTR);
static constexpr int SMEM_BYTES  = SMEM_FLOATS * 4;   // 23808 B

__global__ __launch_bounds__(THREADS, 8)
void fk_kernel(const float* __restrict__ rot,
               const float* __restrict__ jnt,
               float* __restrict__ out_pj,
               float* __restrict__ out_rel)
{
    extern __shared__ float sm[];
    float* sR = sm;                    // [MB][RSTR] local R (read-only after A)
    float* sJ = sR + MB * RSTR;        // [MB][JSTR] joints (read-only after A)
    float* sT = sJ + MB * JSTR;        // [MB][TSTR] global t

    const int tid = threadIdx.x;
    const int blockBatch = blockIdx.x * MB;

    // ---------------- Phase A: whole-block coalesced staging ----------------
    {
        float4* sR4 = reinterpret_cast<float4*>(sR);       // batch stride 55 f4
        const float4* rot4 = reinterpret_cast<const float4*>(rot) + (size_t)blockBatch * 54;
        #pragma unroll
        for (int it = 0; it < 7; ++it) {                   // 16*54 = 864 float4
            int idx = tid + it * THREADS;
            if (idx < MB * 54) {
                int b = idx / 54, rf = idx % 54;
                sR4[b * 55 + rf] = rot4[idx];
            }
        }
        float4* sJ4 = reinterpret_cast<float4*>(sJ);       // batch stride 19 f4
        const float4* jnt4 = reinterpret_cast<const float4*>(jnt) + (size_t)blockBatch * 18;
        #pragma unroll
        for (int it = 0; it < 3; ++it) {                   // 16*18 = 288 float4
            int idx = tid + it * THREADS;
            if (idx < MB * 18) {
                int b = idx / 18, rf = idx % 18;
                sJ4[b * 19 + rf] = jnt4[idx];
            }
        }
    }
    __syncthreads();

    // ------- Phase B: warps 0-1 chain-walk all 16 batches (BPW=8/warp) -------
    if (tid < NCHAIN) {
        constexpr int PAR[NJ]  = {-1,0,0,0,1,2,3,4,5,6,7,8,9,9,9,12,13,14,16,17,18,19,20,21};
        // static 4-slot ring from liveness of PARENTS (max 4 live; -1 = leaf)
        constexpr int SLOT[NJ] = { 0,1,2,3,0,1,2,3,0,1,-1,-1,2,3,0,-1,2,3,0,1,2,3,-1,-1};
        const int  bl     = tid >> 2;           // 0..15 local batch
        const int  r      = tid & 3;
        const bool active = (r < 3);
        float ring[4][4];                       // [slot][Rg_r0,Rg_r1,Rg_r2,t_r]
        float jring[4][3];                      // [slot][j0,j1,j2]
        const float* mR = sR + bl * RSTR;
        const float* mJ = sJ + bl * JSTR;
        float*       mT = sT + bl * TSTR;
        float4* relW = reinterpret_cast<float4*>(out_rel) + (size_t)(blockBatch + bl) * 96;

        #pragma unroll
        for (int i = 0; i < NJ; ++i) {
            float4 v;
            if (active) {
                float row[4];
                const float j0 = mJ[i * 3 + 0];
                const float j1 = mJ[i * 3 + 1];
                const float j2 = mJ[i * 3 + 2];
                if (i == 0) {
                    row[0] = mR[r * 3 + 0];
                    row[1] = mR[r * 3 + 1];
                    row[2] = mR[r * 3 + 2];
                    row[3] = (r == 0) ? j0 : (r == 1) ? j1 : j2;
                } else {
                    const int ps = SLOT[PAR[i]];            // constexpr after unroll
                    const float a0 = ring[ps][0], a1 = ring[ps][1], a2 = ring[ps][2];
                    const float l00 = mR[i*9+0], l01 = mR[i*9+1], l02 = mR[i*9+2];
                    const float l10 = mR[i*9+3], l11 = mR[i*9+4], l12 = mR[i*9+5];
                    const float l20 = mR[i*9+6], l21 = mR[i*9+7], l22 = mR[i*9+8];
                    const float rel0 = j0 - jring[ps][0];
                    const float rel1 = j1 - jring[ps][1];
                    const float rel2 = j2 - jring[ps][2];
                    row[0] = a0 * l00 + a1 * l10 + a2 * l20;
                    row[1] = a0 * l01 + a1 * l11 + a2 * l21;
                    row[2] = a0 * l02 + a1 * l12 + a2 * l22;
                    row[3] = ring[ps][3] + a0 * rel0 + a1 * rel1 + a2 * rel2;
                }
                if (SLOT[i] >= 0) {                         // leaves skip ring writes
                    const int s = SLOT[i];
                    #pragma unroll
                    for (int k = 0; k < 4; ++k) ring[s][k] = row[k];
                    jring[s][0] = j0; jring[s][1] = j1; jring[s][2] = j2;
                }
                mT[i * 3 + r] = row[3];                     // for posed_joints
                v = make_float4(row[0], row[1], row[2],
                                row[3] - (row[0]*j0 + row[1]*j1 + row[2]*j2));
            } else {
                v = make_float4(0.f, 0.f, 0.f, 1.f);        // bottom row
            }
            relW[i * 4 + r] = v;                            // direct rel store
        }
    }
    __syncthreads();

    // ---------------- Phase C: whole-block coalesced posed-joints copy ----------------
    {
        const float4* sT4 = reinterpret_cast<const float4*>(sT);   // batch stride 19 f4
        float4* pj4 = reinterpret_cast<float4*>(out_pj) + (size_t)blockBatch * 18;
        #pragma unroll
        for (int it = 0; it < 3; ++it) {                   // 16*18 = 288 float4
            int idx = tid + it * THREADS;
            if (idx < MB * 18) {
                int b = idx / 18, rf = idx % 18;
                pj4[idx] = sT4[b * 19 + rf];
            }
        }
    }
}

extern "C" void kernel_launch(void* const* d_in, const int* in_sizes, int n_in,
                              void* d_out, int out_size)
{
    const float* rot = (const float*)d_in[0];
    const float* jnt = (const float*)d_in[1];
    float* out = (float*)d_out;

    const long long B = 65536;
    float* out_pj  = out;
    float* out_rel = out + (size_t)B * NJ * 3;

    cudaFuncSetAttribute(fk_kernel, cudaFuncAttributeMaxDynamicSharedMemorySize, SMEM_BYTES);

    const int grid = (int)(B / MB);   // 4096 blocks
    fk_kernel<<<grid, THREADS, SMEM_BYTES>>>(rot, jnt, out_pj, out_rel);
}